// round 13
// baseline (speedup 1.0000x reference)
#include <cuda_runtime.h>
#include <cuda_bf16.h>
#include <cuda_fp16.h>
#include <cstdint>
#include <type_traits>
#include <math_constants.h>

// ---------------- problem-size capacities (fixed by the dataset) -------------
#define NMAX 20000
#define EMAX 30000
#define BMAX 128
#define DIM  64

// ---------------- device scratch (static: no allocations allowed) ------------
__device__ __align__(256) float g_h[NMAX * DIM];
__device__ __align__(256) float g_agg[NMAX * DIM];
// A* fragments: [m16][16 k16][lane][reg]; k16 0-7 = a0, 8-15 = a1
__device__ __align__(256) unsigned g_apack[(size_t)1888 * 16 * 128];
// B* fragments: [16 k16][512 n8][lane][reg]; k16 0-7 = b0, 8-15 = b1
__device__ __align__(256) unsigned g_bpack[(size_t)16 * 512 * 64];
// X* fragments for GRU GEMM: [1256 m16][16 k16][lane][reg]
__device__ __align__(256) unsigned g_xpack[(size_t)1256 * 16 * 128];
// W'' fragments for GRU GEMM: [16 k16][32 n8][lane][reg]
__device__ __align__(256) unsigned g_gpack[16 * 32 * 64];
__device__ __align__(256) float g_gbias[256];
__device__ __align__(256) float g_gates[(size_t)20096 * 256];
__device__ __align__(256) __half g_ew16[(size_t)EMAX * 4096];
__device__ int   g_deg[NMAX];
__device__ float g_invdeg[NMAX];
__device__ __align__(256) float g_s2s_wihT[128 * 256];
__device__ __align__(256) float g_s2s_whhT[DIM * 256];
__device__ float g_e[NMAX];
__device__ int   g_start[BMAX];
__device__ int   g_cnt[BMAX];

__device__ __forceinline__ float sigf(float x) { return 1.f / (1.f + expf(-x)); }
__device__ __forceinline__ unsigned bfpack(float lo, float hi) {
    __nv_bfloat16 l = __float2bfloat16(lo), h = __float2bfloat16(hi);
    return (unsigned)__bfloat16_as_ushort(l) | ((unsigned)__bfloat16_as_ushort(h) << 16);
}

// ---------------- small utility kernels --------------------------------------
__global__ void k_zero_i(int* p, int n) {
    int i = blockIdx.x * blockDim.x + threadIdx.x;
    if (i < n) p[i] = 0;
}
__global__ void k_transpose(float* dst, const float* __restrict__ src, int G, int K) {
    int idx = blockIdx.x * blockDim.x + threadIdx.x;
    if (idx >= G * K) return;
    int g = idx / K, k = idx % K;
    dst[k * G + g] = src[idx];
}

// ---- combined prep: ENN hidden -> A* fragments, and W2 -> B* fragments ------
__global__ void k_prep_all(const float* __restrict__ ef, const float* __restrict__ w1,
                           const float* __restrict__ b1, const float* __restrict__ w2,
                           int E) {
    int idx = blockIdx.x * blockDim.x + threadIdx.x;
    int na = E * 64;
    if (idx < na) {
        int e = idx >> 6, jp = idx & 63;
        int j0 = jp << 1;
        float f[11];
        #pragma unroll
        for (int k = 0; k < 11; k++) f[k] = ef[e * 11 + k];
        float a = b1[j0], b = b1[j0 + 1];
        #pragma unroll
        for (int k = 0; k < 11; k++) {
            a = fmaf(f[k], w1[k * 128 + j0], a);
            b = fmaf(f[k], w1[k * 128 + j0 + 1], b);
        }
        a = fmaxf(a, 0.f);
        b = fmaxf(b, 0.f);
        float a0 = __bfloat162float(__float2bfloat16(a));
        float b0 = __bfloat162float(__float2bfloat16(b));
        unsigned p0 = bfpack(a, b);
        unsigned p1 = bfpack(a - a0, b - b0);
        int m16 = e >> 4, r16 = e & 15;
        int k8 = j0 & 15;
        int lane = ((r16 & 7) << 2) | ((k8 >> 1) & 3);
        int reg = (r16 >> 3) | (((k8 >> 3) & 1) << 1);
        size_t base = ((size_t)m16 * 16 + (j0 >> 4)) * 128 + lane * 4 + reg;
        g_apack[base] = p0;
        g_apack[base + (size_t)8 * 128] = p1;
    } else {
        int idx2 = idx - na;
        if (idx2 >= 128 * 4096) return;
        int kp = idx2 >> 12, n = idx2 & 4095;
        int Ks = kp << 1;
        int region = Ks >> 7;
        int k = Ks & 127;
        float wa = w2[k * 4096 + n], wb = w2[(k + 1) * 4096 + n];
        float va, vb;
        if (region == 1) {
            va = wa - __bfloat162float(__float2bfloat16(wa));
            vb = wb - __bfloat162float(__float2bfloat16(wb));
        } else {
            va = wa; vb = wb;
        }
        unsigned u = bfpack(va, vb);
        int k16 = Ks >> 4, k8 = Ks & 15;
        int lane = ((n & 7) << 2) | ((k8 >> 1) & 3);
        int reg = (k8 >> 3) & 1;
        g_bpack[((k16 * 512 + (n >> 3)) * 32 + lane) * 2 + reg] = u;
    }
}

// ---- GRU stacked-weight prep: W''[128][256] + bias[256] ---------------------
__device__ __forceinline__ float gru_wfull(const float* wih, const float* whh, int k, int c) {
    if (c < 128) return (k < 64) ? wih[c * 64 + k] : whh[c * 64 + (k - 64)];
    if (c < 192) return (k < 64) ? wih[c * 64 + k] : 0.f;
    return (k < 64) ? 0.f : whh[(c - 64) * 64 + (k - 64)];
}
__global__ void k_prep_gruw(const float* __restrict__ wih, const float* __restrict__ whh,
                            const float* __restrict__ bih, const float* __restrict__ bhh) {
    int idx = blockIdx.x * blockDim.x + threadIdx.x;
    if (idx >= 128 * 256) return;
    int kp = idx >> 8, c = idx & 255;
    int Ks = kp << 1;
    int region = Ks >> 7;
    int k = Ks & 127;
    float wa = gru_wfull(wih, whh, k, c), wb = gru_wfull(wih, whh, k + 1, c);
    float va, vb;
    if (region == 1) {
        va = wa - __bfloat162float(__float2bfloat16(wa));
        vb = wb - __bfloat162float(__float2bfloat16(wb));
    } else {
        va = wa; vb = wb;
    }
    unsigned u = bfpack(va, vb);
    int k16 = Ks >> 4, k8 = Ks & 15;
    int lane = ((c & 7) << 2) | ((k8 >> 1) & 3);
    int reg = (k8 >> 3) & 1;
    g_gpack[((k16 * 32 + (c >> 3)) * 32 + lane) * 2 + reg] = u;
    if (kp == 0) {
        float bias;
        if (c < 128) bias = bih[c] + bhh[c];
        else if (c < 192) bias = bih[c];
        else bias = bhh[c - 64];
        g_gbias[c] = bias;
    }
}

// ---------------- lin0: h = relu(nf @ W + b); also zero agg ------------------
__global__ void k_lin0(const float* __restrict__ nf, const float* __restrict__ w,
                       const float* __restrict__ b, int N) {
    int idx = blockIdx.x * blockDim.x + threadIdx.x;
    if (idx >= N * DIM) return;
    int n = idx >> 6, d = idx & 63;
    float acc = b[d];
    #pragma unroll
    for (int k = 0; k < 30; k++) acc = fmaf(nf[n * 30 + k], w[k * DIM + d], acc);
    g_h[idx] = fmaxf(acc, 0.f);
    g_agg[idx] = 0.f;
}

// ---------------- degrees ----------------------------------------------------
__global__ void k_count(const int* __restrict__ ei, int E) {
    int e = blockIdx.x * blockDim.x + threadIdx.x;
    if (e < E) atomicAdd(&g_deg[ei[E + e]], 1);
}
__global__ void k_invdeg(int N) {
    int n = blockIdx.x * blockDim.x + threadIdx.x;
    if (n < N) g_invdeg[n] = 1.f / fmaxf((float)g_deg[n], 1.f);
}

// ---------------- templated fragment GEMM (bf16x3, 3 passes) -----------------
// A fragments loaded DIRECTLY from gmem (A* is already in mma fragment order;
// removes all A STS/LDS — the L1 bottleneck R10/R12 profiles showed). B keeps
// the 4-buffer smem pipeline (32 KB) with one sync per two 32-K stages.
// Pass order a0b0, a1b0, a0b1 retires a1/b registers early (~120 live regs).
#define MMA_ACC(d, a, b) \
    asm volatile("mma.sync.aligned.m16n8k16.row.col.f32.bf16.bf16.f32 " \
                 "{%0,%1,%2,%3}, {%4,%5,%6,%7}, {%8,%9}, {%0,%1,%2,%3};" \
                 : "+f"(d[0]), "+f"(d[1]), "+f"(d[2]), "+f"(d[3]) \
                 : "r"(a[0]), "r"(a[1]), "r"(a[2]), "r"(a[3]), "r"(b[0]), "r"(b[1]))

template <int N8TOT, typename OutT>
__global__ void __launch_bounds__(256, 2) k_gemm_frag(
        const unsigned* __restrict__ Ap, const unsigned* __restrict__ Bp,
        const float* __restrict__ bias, OutT* __restrict__ C, int M) {
    constexpr int LDC = N8TOT * 8;
    extern __shared__ __align__(16) unsigned sm[];   // B only: 4 bufs x 2048 u32
    const int tid = threadIdx.x;
    const int lane = tid & 31, warp = tid >> 5;
    const int wm = warp >> 2, wn = warp & 3;
    const int bm = blockIdx.y << 7, bn = blockIdx.x << 7;
    const uint4* Ap4 = reinterpret_cast<const uint4*>(Ap);
    const uint4* Bp4 = reinterpret_cast<const uint4*>(Bp);

    float acc[4][4][4];
    #pragma unroll
    for (int i = 0; i < 4; i++)
        #pragma unroll
        for (int j = 0; j < 4; j++)
            #pragma unroll
            for (int c = 0; c < 4; c++) acc[i][j][c] = 0.f;

    uint4 rb[2];

    auto LDGB = [&](int s) {
        #pragma unroll
        for (int l = 0; l < 2; l++) {
            int id = tid + (l << 8);
            int quad = id & 15, nt = (id >> 4) & 15, part = id >> 8;
            rb[l] = Bp4[((size_t)(s + part * 8) * N8TOT + (bn >> 3) + nt) * 16 + quad];
        }
    };
    auto STSB = [&](int buf) {
        #pragma unroll
        for (int l = 0; l < 2; l++) {
            int id = tid + (l << 8);
            int quad = id & 15, nt = (id >> 4) & 15, part = id >> 8;
            *reinterpret_cast<uint4*>(sm + buf * 2048 + part * 1024 + nt * 64 + quad * 4) = rb[l];
        }
    };
    auto COMPUTE = [&](int buf, int s) {
        const unsigned* Bb = sm + buf * 2048;
        unsigned b[4][2];
        #pragma unroll
        for (int j = 0; j < 4; j++)
            *reinterpret_cast<uint2*>(b[j]) =
                *reinterpret_cast<const uint2*>(Bb + ((wn << 2) + j) * 64 + lane * 2);
        // A fragments straight from gmem (fragment-ordered)
        unsigned a0[4][4], a1[4][4];
        #pragma unroll
        for (int i = 0; i < 4; i++)
            *reinterpret_cast<uint4*>(a0[i]) =
                Ap4[(((size_t)((bm >> 4) + (wm << 2) + i)) * 16 + s) * 32 + lane];
        #pragma unroll
        for (int i = 0; i < 4; i++)
            *reinterpret_cast<uint4*>(a1[i]) =
                Ap4[(((size_t)((bm >> 4) + (wm << 2) + i)) * 16 + s + 8) * 32 + lane];
        #pragma unroll
        for (int i = 0; i < 4; i++)
            #pragma unroll
            for (int j = 0; j < 4; j++) MMA_ACC(acc[i][j], a0[i], b[j]);
        #pragma unroll
        for (int i = 0; i < 4; i++)
            #pragma unroll
            for (int j = 0; j < 4; j++) MMA_ACC(acc[i][j], a1[i], b[j]);
        // b1 = part1, reuse b registers (b0, a1 dead)
        #pragma unroll
        for (int j = 0; j < 4; j++)
            *reinterpret_cast<uint2*>(b[j]) =
                *reinterpret_cast<const uint2*>(Bb + 1024 + ((wn << 2) + j) * 64 + lane * 2);
        #pragma unroll
        for (int i = 0; i < 4; i++)
            #pragma unroll
            for (int j = 0; j < 4; j++) MMA_ACC(acc[i][j], a0[i], b[j]);
    };

    LDGB(0); STSB(0);
    LDGB(1); STSB(1);
    __syncthreads();
    #pragma unroll 1
    for (int s = 0; s < 8; s += 2) {
        if (s < 6) LDGB(s + 2);
        COMPUTE(s & 3, s);
        if (s < 6) STSB((s + 2) & 3);
        if (s < 6) LDGB(s + 3);
        COMPUTE((s + 1) & 3, s + 1);
        if (s < 6) {
            STSB((s + 3) & 3);
            __syncthreads();
        }
    }

    int g = lane >> 2, tg = lane & 3;
    #pragma unroll
    for (int i = 0; i < 4; i++) {
        int r0 = bm + (wm << 6) + (i << 4) + g;
        #pragma unroll
        for (int j = 0; j < 4; j++) {
            int col = bn + (wn << 5) + (j << 3) + (tg << 1);
            float b0 = bias[col], b1 = bias[col + 1];
            float v0 = acc[i][j][0] + b0, v1 = acc[i][j][1] + b1;
            float v2 = acc[i][j][2] + b0, v3 = acc[i][j][3] + b1;
            if (r0 < M) {
                if constexpr (std::is_same<OutT, __half>::value)
                    *reinterpret_cast<__half2*>(C + (size_t)r0 * LDC + col) = __floats2half2_rn(v0, v1);
                else
                    *reinterpret_cast<float2*>(C + (size_t)r0 * LDC + col) = make_float2(v0, v1);
            }
            if (r0 + 8 < M) {
                if constexpr (std::is_same<OutT, __half>::value)
                    *reinterpret_cast<__half2*>(C + (size_t)(r0 + 8) * LDC + col) = __floats2half2_rn(v2, v3);
                else
                    *reinterpret_cast<float2*>(C + (size_t)(r0 + 8) * LDC + col) = make_float2(v2, v3);
            }
        }
    }
}

// ---------------- per-edge message: 32 thr/edge, shfl feat broadcast ---------
// No smem, no __syncthreads — feat row lives in 2 regs/lane, broadcast by shfl.
__global__ void k_msg(const int* __restrict__ ei, int E) {
    int t = threadIdx.x;
    int eg = t >> 5, tl = t & 31;
    int e = blockIdx.x * 8 + eg;
    if (e >= E) return;                     // uniform per warp
    int src = ei[e];
    float flo = g_h[(size_t)src * DIM + tl];
    float fhi = g_h[(size_t)src * DIM + 32 + tl];
    const __half2* ew = reinterpret_cast<const __half2*>(g_ew16 + (size_t)e * 4096) + tl;
    float acc0 = 0.f, acc1 = 0.f;
    #pragma unroll
    for (int i = 0; i < DIM; i++) {
        float fi = __shfl_sync(0xffffffffu, (i < 32) ? flo : fhi, i & 31);
        float2 w = __half22float2(ew[i * 32]);
        acc0 = fmaf(fi, w.x, acc0);
        acc1 = fmaf(fi, w.y, acc1);
    }
    int dst = ei[E + e];
    atomicAdd(&g_agg[(size_t)dst * DIM + 2 * tl], acc0);
    atomicAdd(&g_agg[(size_t)dst * DIM + 2 * tl + 1], acc1);
}

// ---------------- X* pack for GRU GEMM: X=[m|h] (64 physical pairs) ----------
__global__ void k_xpack(const float* __restrict__ conv_b, int N) {
    int idx = blockIdx.x * blockDim.x + threadIdx.x;
    if (idx >= N * 64) return;
    int n = idx >> 6, jp = idx & 63;
    int j0 = jp << 1;
    float a, b;
    if (j0 < 64) {
        float inv = g_invdeg[n];
        a = fmaxf(fmaf(g_agg[n * 64 + j0], inv, conv_b[j0]), 0.f);
        b = fmaxf(fmaf(g_agg[n * 64 + j0 + 1], inv, conv_b[j0 + 1]), 0.f);
        g_agg[n * 64 + j0] = 0.f;
        g_agg[n * 64 + j0 + 1] = 0.f;
    } else {
        a = g_h[n * 64 + (j0 - 64)];
        b = g_h[n * 64 + (j0 - 63)];
    }
    float a0 = __bfloat162float(__float2bfloat16(a));
    float b0 = __bfloat162float(__float2bfloat16(b));
    unsigned p0 = bfpack(a, b);
    unsigned p1 = bfpack(a - a0, b - b0);
    int m16 = n >> 4, r16 = n & 15;
    int k8 = j0 & 15;
    int lane = ((r16 & 7) << 2) | ((k8 >> 1) & 3);
    int reg = (r16 >> 3) | (((k8 >> 3) & 1) << 1);
    size_t base = ((size_t)m16 * 16 + (j0 >> 4)) * 128 + lane * 4 + reg;
    g_xpack[base] = p0;
    g_xpack[base + (size_t)8 * 128] = p1;
}

// ---------------- GRU combine from stacked gates -----------------------------
__global__ void k_gru_combine(int N) {
    int idx = blockIdx.x * blockDim.x + threadIdx.x;
    if (idx >= N * DIM) return;
    int n = idx >> 6, d = idx & 63;
    const float* g = &g_gates[(size_t)n * 256];
    float r = sigf(g[d]);
    float z = sigf(g[64 + d]);
    float nn = tanhf(fmaf(r, g[192 + d], g[128 + d]));
    float hold = g_h[idx];
    g_h[idx] = fmaf(z, hold - nn, nn);
}

// ---------------- graph segment offsets --------------------------------------
__global__ void k_seg_zero(int B) {
    int b = threadIdx.x;
    if (b < B) { g_start[b] = 0x7fffffff; g_cnt[b] = 0; }
}
__global__ void k_seg_scan(const int* __restrict__ gidx, int N) {
    int n = blockIdx.x * blockDim.x + threadIdx.x;
    if (n >= N) return;
    int g = gidx[n];
    atomicMin(&g_start[g], n);
    atomicAdd(&g_cnt[g], 1);
}

// ---------------- fused Set2Set (3 steps) + FC head: one block per graph -----
__global__ void k_s2s_all(const float* __restrict__ bih, const float* __restrict__ bhh,
                          const float* __restrict__ fc1_w, const float* __restrict__ fc1_b,
                          const float* __restrict__ fc2_w, const float* __restrict__ fc2_b,
                          float* __restrict__ out) {
    int b = blockIdx.x, t = threadIdx.x;
    __shared__ float q_sh[128], h_sh[64], lc_sh[64], gates[256], red[256], rpart[4][64];
    if (t < 128) q_sh[t] = 0.f;
    if (t < 64) { h_sh[t] = 0.f; lc_sh[t] = 0.f; }
    int s = g_start[b], c = g_cnt[b];
    if (s == 0x7fffffff) s = 0;
    __syncthreads();
    for (int step = 0; step < 3; step++) {
        float acc = bih[t] + bhh[t];
        #pragma unroll 8
        for (int k = 0; k < 128; k++) acc = fmaf(q_sh[k], g_s2s_wihT[k * 256 + t], acc);
        #pragma unroll 8
        for (int k = 0; k < 64; k++) acc = fmaf(h_sh[k], g_s2s_whhT[k * 256 + t], acc);
        gates[t] = acc;
        __syncthreads();
        if (t < 64) {
            float ig = sigf(gates[t]), fg = sigf(gates[64 + t]);
            float gg = tanhf(gates[128 + t]), og = sigf(gates[192 + t]);
            float cc = fmaf(fg, lc_sh[t], ig * gg);
            lc_sh[t] = cc;
            h_sh[t] = og * tanhf(cc);
        }
        __syncthreads();
        float lmax = -CUDART_INF_F;
        for (int n = s + t; n < s + c; n += 256) {
            const float* hp = &g_h[(size_t)n * DIM];
            float d = 0.f;
            #pragma unroll 8
            for (int k = 0; k < DIM; k++) d = fmaf(hp[k], h_sh[k], d);
            g_e[n] = d;
            lmax = fmaxf(lmax, d);
        }
        red[t] = lmax;
        __syncthreads();
        for (int off = 128; off > 0; off >>= 1) {
            if (t < off) red[t] = fmaxf(red[t], red[t + off]);
            __syncthreads();
        }
        float emax = red[0];
        __syncthreads();
        float lsum = 0.f;
        for (int n = s + t; n < s + c; n += 256) lsum += expf(g_e[n] - emax);
        red[t] = lsum;
        __syncthreads();
        for (int off = 128; off > 0; off >>= 1) {
            if (t < off) red[t] += red[t + off];
            __syncthreads();
        }
        float inv = red[0] > 0.f ? 1.f / red[0] : 0.f;
        __syncthreads();
        int d = t & 63, sub = t >> 6;
        float acc2 = 0.f;
        for (int n = s + sub; n < s + c; n += 4)
            acc2 = fmaf(expf(g_e[n] - emax), g_h[(size_t)n * DIM + d], acc2);
        rpart[sub][d] = acc2;
        __syncthreads();
        if (t < 64) {
            q_sh[64 + t] = (rpart[0][t] + rpart[1][t] + rpart[2][t] + rpart[3][t]) * inv;
            q_sh[t] = h_sh[t];
        }
        __syncthreads();
    }
    if (t < 64) {
        float acc = fc1_b[t];
        #pragma unroll 8
        for (int k = 0; k < 128; k++) acc = fmaf(q_sh[k], fc1_w[k * DIM + t], acc);
        red[t] = fmaxf(acc, 0.f) * fc2_w[t];
    }
    __syncthreads();
    for (int off = 32; off > 0; off >>= 1) {
        if (t < off) red[t] += red[t + off];
        __syncthreads();
    }
    if (t == 0) out[b] = red[0] + fc2_b[0];
}

// ---------------- launch -----------------------------------------------------
extern "C" void kernel_launch(void* const* d_in, const int* in_sizes, int n_in,
                              void* d_out, int out_size) {
    const int N = in_sizes[0] / 30;
    const int E = in_sizes[1] / 11;
    const int B = out_size;

    const float* nf   = (const float*)d_in[0];
    const float* ef   = (const float*)d_in[1];
    const int*   ei   = (const int*)d_in[2];
    const int*   gidx = (const int*)d_in[3];
    int wb = (in_sizes[4] == 1) ? 5 : 4;
    const float* lin0_w  = (const float*)d_in[wb + 0];
    const float* lin0_b  = (const float*)d_in[wb + 1];
    const float* enn_w1  = (const float*)d_in[wb + 2];
    const float* enn_b1  = (const float*)d_in[wb + 3];
    const float* enn_w2  = (const float*)d_in[wb + 4];
    const float* enn_b2  = (const float*)d_in[wb + 5];
    const float* conv_b  = (const float*)d_in[wb + 6];
    const float* gru_wih = (const float*)d_in[wb + 7];
    const float* gru_whh = (const float*)d_in[wb + 8];
    const float* gru_bih = (const float*)d_in[wb + 9];
    const float* gru_bhh = (const float*)d_in[wb + 10];
    const float* s2s_wih = (const float*)d_in[wb + 11];
    const float* s2s_whh = (const float*)d_in[wb + 12];
    const float* s2s_bih = (const float*)d_in[wb + 13];
    const float* s2s_bhh = (const float*)d_in[wb + 14];
    const float* fc1_w   = (const float*)d_in[wb + 15];
    const float* fc1_b   = (const float*)d_in[wb + 16];
    const float* fc2_w   = (const float*)d_in[wb + 17];
    const float* fc2_b   = (const float*)d_in[wb + 18];
    float* out = (float*)d_out;

    float *p_swihT, *p_swhhT, *p_gbias, *p_gates;
    unsigned *p_ap, *p_bp, *p_xp, *p_gp;
    __half *p_ew;
    cudaGetSymbolAddress((void**)&p_swihT, g_s2s_wihT);
    cudaGetSymbolAddress((void**)&p_swhhT, g_s2s_whhT);
    cudaGetSymbolAddress((void**)&p_ap, g_apack);
    cudaGetSymbolAddress((void**)&p_bp, g_bpack);
    cudaGetSymbolAddress((void**)&p_xp, g_xpack);
    cudaGetSymbolAddress((void**)&p_gp, g_gpack);
    cudaGetSymbolAddress((void**)&p_gbias, g_gbias);
    cudaGetSymbolAddress((void**)&p_gates, g_gates);
    cudaGetSymbolAddress((void**)&p_ew, g_ew16);
    int* p_deg; cudaGetSymbolAddress((void**)&p_deg, g_deg);

    // 1-3 prep; launch 4 = big GEMM (capture target)
    {
        int total = E * 64 + 128 * 4096;
        k_prep_all<<<(total + 255) / 256, 256>>>(ef, enn_w1, enn_b1, enn_w2, E);
    }
    k_prep_gruw<<<(128 * 256 + 255) / 256, 256>>>(gru_wih, gru_whh, gru_bih, gru_bhh);
    k_lin0<<<(N * DIM + 255) / 256, 256>>>(nf, lin0_w, lin0_b, N);
    {
        dim3 grid(4096 / 128, (E + 127) / 128);
        k_gemm_frag<512, __half><<<grid, 256, 32768>>>(p_ap, p_bp, enn_b2, p_ew, E);
    }

    // degrees
    k_zero_i<<<(N + 255) / 256, 256>>>(p_deg, N);
    k_count<<<(E + 255) / 256, 256>>>(ei, E);
    k_invdeg<<<(N + 255) / 256, 256>>>(N);

    // 3 message-passing + GRU iterations (GRU = xpack + GEMM + combine)
    dim3 ggrid(256 / 128, (N + 127) / 128);
    for (int it = 0; it < 3; it++) {
        k_msg<<<(E + 7) / 8, 256>>>(ei, E);
        k_xpack<<<(N * 64 + 255) / 256, 256>>>(conv_b, N);
        k_gemm_frag<32, float><<<ggrid, 256, 32768>>>(p_xp, p_gp, p_gbias, p_gates, N);
        k_gru_combine<<<(N * DIM + 255) / 256, 256>>>(N);
    }

    // Set2Set + FC head
    k_transpose<<<(256 * 128 + 255) / 256, 256>>>(p_swihT, s2s_wih, 256, 128);
    k_transpose<<<(256 * 64 + 255) / 256, 256>>>(p_swhhT, s2s_whh, 256, 64);
    k_seg_zero<<<1, 128>>>(B);
    k_seg_scan<<<(N + 255) / 256, 256>>>(gidx, N);
    k_s2s_all<<<B, 256>>>(s2s_bih, s2s_bhh, fc1_w, fc1_b, fc2_w, fc2_b, out);
}

// round 14
// speedup vs baseline: 1.0719x; 1.0719x over previous
#include <cuda_runtime.h>
#include <cuda_bf16.h>
#include <cuda_fp16.h>
#include <cstdint>
#include <type_traits>
#include <math_constants.h>

// ---------------- problem-size capacities (fixed by the dataset) -------------
#define NMAX 20000
#define EMAX 30000
#define BMAX 128
#define DIM  64

// ---------------- device scratch (static: no allocations allowed) ------------
__device__ __align__(256) float g_h[NMAX * DIM];
__device__ __align__(256) float g_agg[NMAX * DIM];
// A* fragments: [m16][16 k16][lane][reg]; k16 0-7 = a0, 8-15 = a1
__device__ __align__(256) unsigned g_apack[(size_t)1888 * 16 * 128];
// B* fragments: [16 k16][512 n8][lane][reg]; k16 0-7 = b0, 8-15 = b1
__device__ __align__(256) unsigned g_bpack[(size_t)16 * 512 * 64];
// X* fragments for GRU GEMM: [1256 m16][16 k16][lane][reg]
__device__ __align__(256) unsigned g_xpack[(size_t)1256 * 16 * 128];
// W'' fragments for GRU GEMM: [16 k16][32 n8][lane][reg]
__device__ __align__(256) unsigned g_gpack[16 * 32 * 64];
__device__ __align__(256) float g_gbias[256];
__device__ __align__(256) float g_gates[(size_t)20096 * 256];
__device__ __align__(256) __half g_ew16[(size_t)EMAX * 4096];
__device__ int   g_deg[NMAX];
__device__ __align__(256) float g_s2s_wihT[128 * 256];
__device__ __align__(256) float g_s2s_whhT[DIM * 256];
__device__ float g_e[NMAX];
__device__ int   g_start[BMAX];
__device__ int   g_cnt[BMAX];

__device__ __forceinline__ float sigf(float x) { return 1.f / (1.f + expf(-x)); }
__device__ __forceinline__ unsigned bfpack(float lo, float hi) {
    __nv_bfloat16 l = __float2bfloat16(lo), h = __float2bfloat16(hi);
    return (unsigned)__bfloat16_as_ushort(l) | ((unsigned)__bfloat16_as_ushort(h) << 16);
}

// ---------------- small utility kernels --------------------------------------
__global__ void k_transpose(float* dst, const float* __restrict__ src, int G, int K) {
    int idx = blockIdx.x * blockDim.x + threadIdx.x;
    if (idx >= G * K) return;
    int g = idx / K, k = idx % K;
    dst[k * G + g] = src[idx];
}

// ---- combined prep: ENN hidden -> A* fragments, W2 -> B* fragments; ALSO ----
// zeros g_deg and inits g_start/g_cnt (idle-thread side tasks; deletes 3
// separate launches from the graph).
__global__ void k_prep_all(const float* __restrict__ ef, const float* __restrict__ w1,
                           const float* __restrict__ b1, const float* __restrict__ w2,
                           int E, int N) {
    int idx = blockIdx.x * blockDim.x + threadIdx.x;
    if (idx < N) g_deg[idx] = 0;
    if (idx < BMAX) { g_start[idx] = 0x7fffffff; g_cnt[idx] = 0; }
    int na = E * 64;
    if (idx < na) {
        int e = idx >> 6, jp = idx & 63;
        int j0 = jp << 1;
        float f[11];
        #pragma unroll
        for (int k = 0; k < 11; k++) f[k] = ef[e * 11 + k];
        float a = b1[j0], b = b1[j0 + 1];
        #pragma unroll
        for (int k = 0; k < 11; k++) {
            a = fmaf(f[k], w1[k * 128 + j0], a);
            b = fmaf(f[k], w1[k * 128 + j0 + 1], b);
        }
        a = fmaxf(a, 0.f);
        b = fmaxf(b, 0.f);
        float a0 = __bfloat162float(__float2bfloat16(a));
        float b0 = __bfloat162float(__float2bfloat16(b));
        unsigned p0 = bfpack(a, b);
        unsigned p1 = bfpack(a - a0, b - b0);
        int m16 = e >> 4, r16 = e & 15;
        int k8 = j0 & 15;
        int lane = ((r16 & 7) << 2) | ((k8 >> 1) & 3);
        int reg = (r16 >> 3) | (((k8 >> 3) & 1) << 1);
        size_t base = ((size_t)m16 * 16 + (j0 >> 4)) * 128 + lane * 4 + reg;
        g_apack[base] = p0;
        g_apack[base + (size_t)8 * 128] = p1;
    } else {
        int idx2 = idx - na;
        if (idx2 >= 128 * 4096) return;
        int kp = idx2 >> 12, n = idx2 & 4095;
        int Ks = kp << 1;
        int region = Ks >> 7;
        int k = Ks & 127;
        float wa = w2[k * 4096 + n], wb = w2[(k + 1) * 4096 + n];
        float va, vb;
        if (region == 1) {
            va = wa - __bfloat162float(__float2bfloat16(wa));
            vb = wb - __bfloat162float(__float2bfloat16(wb));
        } else {
            va = wa; vb = wb;
        }
        unsigned u = bfpack(va, vb);
        int k16 = Ks >> 4, k8 = Ks & 15;
        int lane = ((n & 7) << 2) | ((k8 >> 1) & 3);
        int reg = (k8 >> 3) & 1;
        g_bpack[((k16 * 512 + (n >> 3)) * 32 + lane) * 2 + reg] = u;
    }
}

// ---- GRU stacked-weight prep: W''[128][256] + bias[256] ---------------------
__device__ __forceinline__ float gru_wfull(const float* wih, const float* whh, int k, int c) {
    if (c < 128) return (k < 64) ? wih[c * 64 + k] : whh[c * 64 + (k - 64)];
    if (c < 192) return (k < 64) ? wih[c * 64 + k] : 0.f;
    return (k < 64) ? 0.f : whh[(c - 64) * 64 + (k - 64)];
}
__global__ void k_prep_gruw(const float* __restrict__ wih, const float* __restrict__ whh,
                            const float* __restrict__ bih, const float* __restrict__ bhh) {
    int idx = blockIdx.x * blockDim.x + threadIdx.x;
    if (idx >= 128 * 256) return;
    int kp = idx >> 8, c = idx & 255;
    int Ks = kp << 1;
    int region = Ks >> 7;
    int k = Ks & 127;
    float wa = gru_wfull(wih, whh, k, c), wb = gru_wfull(wih, whh, k + 1, c);
    float va, vb;
    if (region == 1) {
        va = wa - __bfloat162float(__float2bfloat16(wa));
        vb = wb - __bfloat162float(__float2bfloat16(wb));
    } else {
        va = wa; vb = wb;
    }
    unsigned u = bfpack(va, vb);
    int k16 = Ks >> 4, k8 = Ks & 15;
    int lane = ((c & 7) << 2) | ((k8 >> 1) & 3);
    int reg = (k8 >> 3) & 1;
    g_gpack[((k16 * 32 + (c >> 3)) * 32 + lane) * 2 + reg] = u;
    if (kp == 0) {
        float bias;
        if (c < 128) bias = bih[c] + bhh[c];
        else if (c < 192) bias = bih[c];
        else bias = bhh[c - 64];
        g_gbias[c] = bias;
    }
}

// ---------------- lin0: h = relu(nf @ W + b); also zero agg ------------------
__global__ void k_lin0(const float* __restrict__ nf, const float* __restrict__ w,
                       const float* __restrict__ b, int N) {
    int idx = blockIdx.x * blockDim.x + threadIdx.x;
    if (idx >= N * DIM) return;
    int n = idx >> 6, d = idx & 63;
    float acc = b[d];
    #pragma unroll
    for (int k = 0; k < 30; k++) acc = fmaf(nf[n * 30 + k], w[k * DIM + d], acc);
    g_h[idx] = fmaxf(acc, 0.f);
    g_agg[idx] = 0.f;
}

// ---------------- degrees ----------------------------------------------------
__global__ void k_count(const int* __restrict__ ei, int E) {
    int e = blockIdx.x * blockDim.x + threadIdx.x;
    if (e < E) atomicAdd(&g_deg[ei[E + e]], 1);
}

// ---------------- templated fragment GEMM (R12-verified, bf16x3, 3 passes) ---
// 4-buffer smem pipeline for A and B, one __syncthreads per TWO 32-K stages,
// forced 2-CTA/SM residency.
template <int N8TOT, typename OutT>
__global__ void __launch_bounds__(256, 2) k_gemm_frag(
        const unsigned* __restrict__ Ap, const unsigned* __restrict__ Bp,
        const float* __restrict__ bias, OutT* __restrict__ C, int M) {
    constexpr int LDC = N8TOT * 8;
    extern __shared__ __align__(16) unsigned sm[];
    const int tid = threadIdx.x;
    const int lane = tid & 31, warp = tid >> 5;
    const int wm = warp >> 2, wn = warp & 3;
    const int bm = blockIdx.y << 7, bn = blockIdx.x << 7;
    const uint4* Ap4 = reinterpret_cast<const uint4*>(Ap);
    const uint4* Bp4 = reinterpret_cast<const uint4*>(Bp);

    float acc[4][4][4];
    #pragma unroll
    for (int i = 0; i < 4; i++)
        #pragma unroll
        for (int j = 0; j < 4; j++)
            #pragma unroll
            for (int c = 0; c < 4; c++) acc[i][j][c] = 0.f;

    uint4 ra[2], rb[2];

    auto LDG = [&](int s) {
        #pragma unroll
        for (int l = 0; l < 2; l++) {
            int id = tid + (l << 8);
            {
                int la = id & 31, mt = (id >> 5) & 7, part = id >> 8;
                ra[l] = Ap4[(((size_t)((bm >> 4) + mt)) * 16 + (s + part * 8)) * 32 + la];
            }
            {
                int quad = id & 15, nt = (id >> 4) & 15, part = id >> 8;
                rb[l] = Bp4[((size_t)(s + part * 8) * N8TOT + (bn >> 3) + nt) * 16 + quad];
            }
        }
    };
    auto STS = [&](int buf) {
        #pragma unroll
        for (int l = 0; l < 2; l++) {
            int id = tid + (l << 8);
            {
                int la = id & 31, mt = (id >> 5) & 7, part = id >> 8;
                *reinterpret_cast<uint4*>(sm + buf * 2048 + part * 1024 + mt * 128 + la * 4) = ra[l];
            }
            {
                int quad = id & 15, nt = (id >> 4) & 15, part = id >> 8;
                *reinterpret_cast<uint4*>(sm + 8192 + buf * 2048 + part * 1024 + nt * 64 + quad * 4) = rb[l];
            }
        }
    };
    auto COMPUTE = [&](int buf) {
        unsigned a[4][4], b0[4][2], b1[4][2];
        const unsigned* Bb = sm + 8192 + buf * 2048;
        #pragma unroll
        for (int j = 0; j < 4; j++) {
            *reinterpret_cast<uint2*>(b0[j]) =
                *reinterpret_cast<const uint2*>(Bb + ((wn << 2) + j) * 64 + lane * 2);
            *reinterpret_cast<uint2*>(b1[j]) =
                *reinterpret_cast<const uint2*>(Bb + 1024 + ((wn << 2) + j) * 64 + lane * 2);
        }
        const unsigned* Ab = sm + buf * 2048;
        #pragma unroll
        for (int i = 0; i < 4; i++)
            *reinterpret_cast<uint4*>(a[i]) =
                *reinterpret_cast<const uint4*>(Ab + ((wm << 2) + i) * 128 + lane * 4);
        #pragma unroll
        for (int i = 0; i < 4; i++)
            #pragma unroll
            for (int j = 0; j < 4; j++)
                asm volatile(
                    "mma.sync.aligned.m16n8k16.row.col.f32.bf16.bf16.f32 "
                    "{%0,%1,%2,%3}, {%4,%5,%6,%7}, {%8,%9}, {%0,%1,%2,%3};"
                    : "+f"(acc[i][j][0]), "+f"(acc[i][j][1]),
                      "+f"(acc[i][j][2]), "+f"(acc[i][j][3])
                    : "r"(a[i][0]), "r"(a[i][1]), "r"(a[i][2]), "r"(a[i][3]),
                      "r"(b0[j][0]), "r"(b0[j][1]));
        #pragma unroll
        for (int i = 0; i < 4; i++)
            #pragma unroll
            for (int j = 0; j < 4; j++)
                asm volatile(
                    "mma.sync.aligned.m16n8k16.row.col.f32.bf16.bf16.f32 "
                    "{%0,%1,%2,%3}, {%4,%5,%6,%7}, {%8,%9}, {%0,%1,%2,%3};"
                    : "+f"(acc[i][j][0]), "+f"(acc[i][j][1]),
                      "+f"(acc[i][j][2]), "+f"(acc[i][j][3])
                    : "r"(a[i][0]), "r"(a[i][1]), "r"(a[i][2]), "r"(a[i][3]),
                      "r"(b1[j][0]), "r"(b1[j][1]));
        #pragma unroll
        for (int i = 0; i < 4; i++)
            *reinterpret_cast<uint4*>(a[i]) =
                *reinterpret_cast<const uint4*>(Ab + 1024 + ((wm << 2) + i) * 128 + lane * 4);
        #pragma unroll
        for (int i = 0; i < 4; i++)
            #pragma unroll
            for (int j = 0; j < 4; j++)
                asm volatile(
                    "mma.sync.aligned.m16n8k16.row.col.f32.bf16.bf16.f32 "
                    "{%0,%1,%2,%3}, {%4,%5,%6,%7}, {%8,%9}, {%0,%1,%2,%3};"
                    : "+f"(acc[i][j][0]), "+f"(acc[i][j][1]),
                      "+f"(acc[i][j][2]), "+f"(acc[i][j][3])
                    : "r"(a[i][0]), "r"(a[i][1]), "r"(a[i][2]), "r"(a[i][3]),
                      "r"(b0[j][0]), "r"(b0[j][1]));
    };

    LDG(0); STS(0);
    LDG(1); STS(1);
    __syncthreads();
    #pragma unroll 1
    for (int s = 0; s < 8; s += 2) {
        if (s < 6) LDG(s + 2);
        COMPUTE(s & 3);
        if (s < 6) STS((s + 2) & 3);
        if (s < 6) LDG(s + 3);
        COMPUTE((s + 1) & 3);
        if (s < 6) {
            STS((s + 3) & 3);
            __syncthreads();
        }
    }

    int g = lane >> 2, tg = lane & 3;
    #pragma unroll
    for (int i = 0; i < 4; i++) {
        int r0 = bm + (wm << 6) + (i << 4) + g;
        #pragma unroll
        for (int j = 0; j < 4; j++) {
            int col = bn + (wn << 5) + (j << 3) + (tg << 1);
            float b0 = bias[col], b1 = bias[col + 1];
            float v0 = acc[i][j][0] + b0, v1 = acc[i][j][1] + b1;
            float v2 = acc[i][j][2] + b0, v3 = acc[i][j][3] + b1;
            if (r0 < M) {
                if constexpr (std::is_same<OutT, __half>::value)
                    *reinterpret_cast<__half2*>(C + (size_t)r0 * LDC + col) = __floats2half2_rn(v0, v1);
                else
                    *reinterpret_cast<float2*>(C + (size_t)r0 * LDC + col) = make_float2(v0, v1);
            }
            if (r0 + 8 < M) {
                if constexpr (std::is_same<OutT, __half>::value)
                    *reinterpret_cast<__half2*>(C + (size_t)(r0 + 8) * LDC + col) = __floats2half2_rn(v2, v3);
                else
                    *reinterpret_cast<float2*>(C + (size_t)(r0 + 8) * LDC + col) = make_float2(v2, v3);
            }
        }
    }
}

// ---------------- per-edge message (R12-verified): 32 thr/edge, half2 loads --
__global__ void k_msg(const int* __restrict__ ei, int E) {
    __shared__ float f_sh[8][DIM];
    int t = threadIdx.x;
    int eg = t >> 5, tl = t & 31;
    int e = blockIdx.x * 8 + eg;
    if (e < E) {
        int src = ei[e];
        f_sh[eg][tl] = g_h[(size_t)src * DIM + tl];
        f_sh[eg][tl + 32] = g_h[(size_t)src * DIM + tl + 32];
    }
    __syncthreads();
    if (e >= E) return;
    const __half2* ew = reinterpret_cast<const __half2*>(g_ew16 + (size_t)e * 4096) + tl;
    const float* f = f_sh[eg];
    float acc0 = 0.f, acc1 = 0.f;
    #pragma unroll
    for (int i = 0; i < DIM; i++) {
        float2 w = __half22float2(ew[i * 32]);
        acc0 = fmaf(f[i], w.x, acc0);
        acc1 = fmaf(f[i], w.y, acc1);
    }
    int dst = ei[E + e];
    atomicAdd(&g_agg[(size_t)dst * DIM + 2 * tl], acc0);
    atomicAdd(&g_agg[(size_t)dst * DIM + 2 * tl + 1], acc1);
}

// ---------------- X* pack for GRU GEMM: X=[m|h]; inv-deg computed inline -----
__global__ void k_xpack(const float* __restrict__ conv_b, int N) {
    int idx = blockIdx.x * blockDim.x + threadIdx.x;
    if (idx >= N * 64) return;
    int n = idx >> 6, jp = idx & 63;
    int j0 = jp << 1;
    float a, b;
    if (j0 < 64) {
        float inv = 1.f / fmaxf((float)g_deg[n], 1.f);
        a = fmaxf(fmaf(g_agg[n * 64 + j0], inv, conv_b[j0]), 0.f);
        b = fmaxf(fmaf(g_agg[n * 64 + j0 + 1], inv, conv_b[j0 + 1]), 0.f);
        g_agg[n * 64 + j0] = 0.f;
        g_agg[n * 64 + j0 + 1] = 0.f;
    } else {
        a = g_h[n * 64 + (j0 - 64)];
        b = g_h[n * 64 + (j0 - 63)];
    }
    float a0 = __bfloat162float(__float2bfloat16(a));
    float b0 = __bfloat162float(__float2bfloat16(b));
    unsigned p0 = bfpack(a, b);
    unsigned p1 = bfpack(a - a0, b - b0);
    int m16 = n >> 4, r16 = n & 15;
    int k8 = j0 & 15;
    int lane = ((r16 & 7) << 2) | ((k8 >> 1) & 3);
    int reg = (r16 >> 3) | (((k8 >> 3) & 1) << 1);
    size_t base = ((size_t)m16 * 16 + (j0 >> 4)) * 128 + lane * 4 + reg;
    g_xpack[base] = p0;
    g_xpack[base + (size_t)8 * 128] = p1;
}

// ---------------- GRU combine from stacked gates -----------------------------
__global__ void k_gru_combine(int N) {
    int idx = blockIdx.x * blockDim.x + threadIdx.x;
    if (idx >= N * DIM) return;
    int n = idx >> 6, d = idx & 63;
    const float* g = &g_gates[(size_t)n * 256];
    float r = sigf(g[d]);
    float z = sigf(g[64 + d]);
    float nn = tanhf(fmaf(r, g[192 + d], g[128 + d]));
    float hold = g_h[idx];
    g_h[idx] = fmaf(z, hold - nn, nn);
}

// ---------------- graph segment scan (start/cnt pre-inited in prep_all) ------
__global__ void k_seg_scan(const int* __restrict__ gidx, int N) {
    int n = blockIdx.x * blockDim.x + threadIdx.x;
    if (n >= N) return;
    int g = gidx[n];
    atomicMin(&g_start[g], n);
    atomicAdd(&g_cnt[g], 1);
}

// ---------------- fused Set2Set (3 steps) + FC head: one block per graph -----
__global__ void k_s2s_all(const float* __restrict__ bih, const float* __restrict__ bhh,
                          const float* __restrict__ fc1_w, const float* __restrict__ fc1_b,
                          const float* __restrict__ fc2_w, const float* __restrict__ fc2_b,
                          float* __restrict__ out) {
    int b = blockIdx.x, t = threadIdx.x;
    __shared__ float q_sh[128], h_sh[64], lc_sh[64], gates[256], red[256], rpart[4][64];
    if (t < 128) q_sh[t] = 0.f;
    if (t < 64) { h_sh[t] = 0.f; lc_sh[t] = 0.f; }
    int s = g_start[b], c = g_cnt[b];
    if (s == 0x7fffffff) s = 0;
    __syncthreads();
    for (int step = 0; step < 3; step++) {
        float acc = bih[t] + bhh[t];
        #pragma unroll 8
        for (int k = 0; k < 128; k++) acc = fmaf(q_sh[k], g_s2s_wihT[k * 256 + t], acc);
        #pragma unroll 8
        for (int k = 0; k < 64; k++) acc = fmaf(h_sh[k], g_s2s_whhT[k * 256 + t], acc);
        gates[t] = acc;
        __syncthreads();
        if (t < 64) {
            float ig = sigf(gates[t]), fg = sigf(gates[64 + t]);
            float gg = tanhf(gates[128 + t]), og = sigf(gates[192 + t]);
            float cc = fmaf(fg, lc_sh[t], ig * gg);
            lc_sh[t] = cc;
            h_sh[t] = og * tanhf(cc);
        }
        __syncthreads();
        float lmax = -CUDART_INF_F;
        for (int n = s + t; n < s + c; n += 256) {
            const float* hp = &g_h[(size_t)n * DIM];
            float d = 0.f;
            #pragma unroll 8
            for (int k = 0; k < DIM; k++) d = fmaf(hp[k], h_sh[k], d);
            g_e[n] = d;
            lmax = fmaxf(lmax, d);
        }
        red[t] = lmax;
        __syncthreads();
        for (int off = 128; off > 0; off >>= 1) {
            if (t < off) red[t] = fmaxf(red[t], red[t + off]);
            __syncthreads();
        }
        float emax = red[0];
        __syncthreads();
        float lsum = 0.f;
        for (int n = s + t; n < s + c; n += 256) lsum += expf(g_e[n] - emax);
        red[t] = lsum;
        __syncthreads();
        for (int off = 128; off > 0; off >>= 1) {
            if (t < off) red[t] += red[t + off];
            __syncthreads();
        }
        float inv = red[0] > 0.f ? 1.f / red[0] : 0.f;
        __syncthreads();
        int d = t & 63, sub = t >> 6;
        float acc2 = 0.f;
        for (int n = s + sub; n < s + c; n += 4)
            acc2 = fmaf(expf(g_e[n] - emax), g_h[(size_t)n * DIM + d], acc2);
        rpart[sub][d] = acc2;
        __syncthreads();
        if (t < 64) {
            q_sh[64 + t] = (rpart[0][t] + rpart[1][t] + rpart[2][t] + rpart[3][t]) * inv;
            q_sh[t] = h_sh[t];
        }
        __syncthreads();
    }
    if (t < 64) {
        float acc = fc1_b[t];
        #pragma unroll 8
        for (int k = 0; k < 128; k++) acc = fmaf(q_sh[k], fc1_w[k * DIM + t], acc);
        red[t] = fmaxf(acc, 0.f) * fc2_w[t];
    }
    __syncthreads();
    for (int off = 32; off > 0; off >>= 1) {
        if (t < off) red[t] += red[t + off];
        __syncthreads();
    }
    if (t == 0) out[b] = red[0] + fc2_b[0];
}

// ---------------- launch -----------------------------------------------------
extern "C" void kernel_launch(void* const* d_in, const int* in_sizes, int n_in,
                              void* d_out, int out_size) {
    const int N = in_sizes[0] / 30;
    const int E = in_sizes[1] / 11;
    const int B = out_size;

    const float* nf   = (const float*)d_in[0];
    const float* ef   = (const float*)d_in[1];
    const int*   ei   = (const int*)d_in[2];
    const int*   gidx = (const int*)d_in[3];
    int wb = (in_sizes[4] == 1) ? 5 : 4;
    const float* lin0_w  = (const float*)d_in[wb + 0];
    const float* lin0_b  = (const float*)d_in[wb + 1];
    const float* enn_w1  = (const float*)d_in[wb + 2];
    const float* enn_b1  = (const float*)d_in[wb + 3];
    const float* enn_w2  = (const float*)d_in[wb + 4];
    const float* enn_b2  = (const float*)d_in[wb + 5];
    const float* conv_b  = (const float*)d_in[wb + 6];
    const float* gru_wih = (const float*)d_in[wb + 7];
    const float* gru_whh = (const float*)d_in[wb + 8];
    const float* gru_bih = (const float*)d_in[wb + 9];
    const float* gru_bhh = (const float*)d_in[wb + 10];
    const float* s2s_wih = (const float*)d_in[wb + 11];
    const float* s2s_whh = (const float*)d_in[wb + 12];
    const float* s2s_bih = (const float*)d_in[wb + 13];
    const float* s2s_bhh = (const float*)d_in[wb + 14];
    const float* fc1_w   = (const float*)d_in[wb + 15];
    const float* fc1_b   = (const float*)d_in[wb + 16];
    const float* fc2_w   = (const float*)d_in[wb + 17];
    const float* fc2_b   = (const float*)d_in[wb + 18];
    float* out = (float*)d_out;

    float *p_swihT, *p_swhhT, *p_gbias, *p_gates;
    unsigned *p_ap, *p_bp, *p_xp, *p_gp;
    __half *p_ew;
    cudaGetSymbolAddress((void**)&p_swihT, g_s2s_wihT);
    cudaGetSymbolAddress((void**)&p_swhhT, g_s2s_whhT);
    cudaGetSymbolAddress((void**)&p_ap, g_apack);
    cudaGetSymbolAddress((void**)&p_bp, g_bpack);
    cudaGetSymbolAddress((void**)&p_xp, g_xpack);
    cudaGetSymbolAddress((void**)&p_gp, g_gpack);
    cudaGetSymbolAddress((void**)&p_gbias, g_gbias);
    cudaGetSymbolAddress((void**)&p_gates, g_gates);
    cudaGetSymbolAddress((void**)&p_ew, g_ew16);

    cudaFuncSetAttribute(k_gemm_frag<512, __half>,
                         cudaFuncAttributeMaxDynamicSharedMemorySize, 65536);
    cudaFuncSetAttribute(k_gemm_frag<32, float>,
                         cudaFuncAttributeMaxDynamicSharedMemorySize, 65536);

    // launches 1-3, then slot 4 = k_msg (this round's profile target)
    {
        int total = E * 64 + 128 * 4096;
        k_prep_all<<<(total + 255) / 256, 256>>>(ef, enn_w1, enn_b1, enn_w2, E, N);
    }
    k_lin0<<<(N * DIM + 255) / 256, 256>>>(nf, lin0_w, lin0_b, N);
    {
        dim3 grid(4096 / 128, (E + 127) / 128);
        k_gemm_frag<512, __half><<<grid, 256, 65536>>>(p_ap, p_bp, enn_b2, p_ew, E);
    }
    k_msg<<<(E + 7) / 8, 256>>>(ei, E);          // iteration-1 message pass

    // degree count + GRU weight prep + segment scan (needed before xpack/s2s)
    k_prep_gruw<<<(128 * 256 + 255) / 256, 256>>>(gru_wih, gru_whh, gru_bih, gru_bhh);
    k_count<<<(E + 255) / 256, 256>>>(ei, E);
    k_seg_scan<<<(N + 255) / 256, 256>>>(gidx, N);

    // GRU iteration 1 tail, then iterations 2-3
    dim3 ggrid(256 / 128, (N + 127) / 128);
    k_xpack<<<(N * 64 + 255) / 256, 256>>>(conv_b, N);
    k_gemm_frag<32, float><<<ggrid, 256, 65536>>>(p_xp, p_gp, p_gbias, p_gates, N);
    k_gru_combine<<<(N * DIM + 255) / 256, 256>>>(N);
    for (int it = 1; it < 3; it++) {
        k_msg<<<(E + 7) / 8, 256>>>(ei, E);
        k_xpack<<<(N * 64 + 255) / 256, 256>>>(conv_b, N);
        k_gemm_frag<32, float><<<ggrid, 256, 65536>>>(p_xp, p_gp, p_gbias, p_gates, N);
        k_gru_combine<<<(N * DIM + 255) / 256, 256>>>(N);
    }

    // Set2Set + FC head
    k_transpose<<<(256 * 128 + 255) / 256, 256>>>(p_swihT, s2s_wih, 256, 128);
    k_transpose<<<(256 * 64 + 255) / 256, 256>>>(p_swhhT, s2s_whh, 256, 64);
    k_s2s_all<<<B, 256>>>(s2s_bih, s2s_bhh, fc1_w, fc1_b, fc2_w, fc2_b, out);
}

// round 15
// speedup vs baseline: 1.0949x; 1.0214x over previous
#include <cuda_runtime.h>
#include <cuda_bf16.h>
#include <cuda_fp16.h>
#include <cstdint>
#include <type_traits>
#include <math_constants.h>

// ---------------- problem-size capacities (fixed by the dataset) -------------
#define NMAX 20000
#define EMAX 30000
#define BMAX 128
#define DIM  64

// ---------------- device scratch (static: no allocations allowed) ------------
__device__ __align__(256) float g_h[NMAX * DIM];
__device__ __align__(256) float g_agg[NMAX * DIM];
// A* fragments: [m16][16 k16][lane][reg]; k16 0-7 = a0, 8-15 = a1
__device__ __align__(256) unsigned g_apack[(size_t)1888 * 16 * 128];
// B* fragments: [16 k16][512 n8][lane][reg]; k16 0-7 = b0, 8-15 = b1
__device__ __align__(256) unsigned g_bpack[(size_t)16 * 512 * 64];
// X* fragments for GRU GEMM: [1256 m16][16 k16][lane][reg]
__device__ __align__(256) unsigned g_xpack[(size_t)1256 * 16 * 128];
// W'' fragments for GRU GEMM: [16 k16][32 n8][lane][reg]
__device__ __align__(256) unsigned g_gpack[16 * 32 * 64];
__device__ __align__(256) float g_gbias[256];
__device__ __align__(256) float g_gates[(size_t)20096 * 256];
__device__ __align__(256) __half g_ew16[(size_t)EMAX * 4096];
__device__ int   g_deg[NMAX];
__device__ __align__(256) float g_s2s_wihT[128 * 256];
__device__ __align__(256) float g_s2s_whhT[DIM * 256];
__device__ float g_e[NMAX];
__device__ int   g_start[BMAX];
__device__ int   g_cnt[BMAX];

__device__ __forceinline__ float sigf(float x) { return 1.f / (1.f + expf(-x)); }
__device__ __forceinline__ unsigned bfpack(float lo, float hi) {
    __nv_bfloat16 l = __float2bfloat16(lo), h = __float2bfloat16(hi);
    return (unsigned)__bfloat16_as_ushort(l) | ((unsigned)__bfloat16_as_ushort(h) << 16);
}

// ---- GRU stacked-weight helper ----------------------------------------------
__device__ __forceinline__ float gru_wfull(const float* wih, const float* whh, int k, int c) {
    if (c < 128) return (k < 64) ? wih[c * 64 + k] : whh[c * 64 + (k - 64)];
    if (c < 192) return (k < 64) ? wih[c * 64 + k] : 0.f;
    return (k < 64) ? 0.f : whh[(c - 64) * 64 + (k - 64)];
}

// ---- mega-prep: ENN->A* fragments, W2->B* fragments, GRU W''->fragments, ----
// s2s weight transposes, deg zero, start/cnt init. One launch, range dispatch.
__global__ void k_prep_all(const float* __restrict__ ef, const float* __restrict__ w1,
                           const float* __restrict__ b1, const float* __restrict__ w2,
                           const float* __restrict__ gru_wih, const float* __restrict__ gru_whh,
                           const float* __restrict__ gru_bih, const float* __restrict__ gru_bhh,
                           const float* __restrict__ s2s_wih, const float* __restrict__ s2s_whh,
                           int E, int N) {
    int idx = blockIdx.x * blockDim.x + threadIdx.x;
    if (idx < N) g_deg[idx] = 0;
    if (idx < BMAX) { g_start[idx] = 0x7fffffff; g_cnt[idx] = 0; }
    int na = E * 64;
    if (idx < na) {
        // ENN hidden: a = relu(ef@W1+b1) -> A* fragments (bf16x2 split)
        int e = idx >> 6, jp = idx & 63;
        int j0 = jp << 1;
        float f[11];
        #pragma unroll
        for (int k = 0; k < 11; k++) f[k] = ef[e * 11 + k];
        float a = b1[j0], b = b1[j0 + 1];
        #pragma unroll
        for (int k = 0; k < 11; k++) {
            a = fmaf(f[k], w1[k * 128 + j0], a);
            b = fmaf(f[k], w1[k * 128 + j0 + 1], b);
        }
        a = fmaxf(a, 0.f);
        b = fmaxf(b, 0.f);
        float a0 = __bfloat162float(__float2bfloat16(a));
        float b0 = __bfloat162float(__float2bfloat16(b));
        unsigned p0 = bfpack(a, b);
        unsigned p1 = bfpack(a - a0, b - b0);
        int m16 = e >> 4, r16 = e & 15;
        int k8 = j0 & 15;
        int lane = ((r16 & 7) << 2) | ((k8 >> 1) & 3);
        int reg = (r16 >> 3) | (((k8 >> 3) & 1) << 1);
        size_t base = ((size_t)m16 * 16 + (j0 >> 4)) * 128 + lane * 4 + reg;
        g_apack[base] = p0;
        g_apack[base + (size_t)8 * 128] = p1;
        return;
    }
    int idx2 = idx - na;
    if (idx2 < 128 * 4096) {
        // W2 -> B* fragments (bf16x2 split, [b0;b1])
        int kp = idx2 >> 12, n = idx2 & 4095;
        int Ks = kp << 1;
        int region = Ks >> 7;
        int k = Ks & 127;
        float wa = w2[k * 4096 + n], wb = w2[(k + 1) * 4096 + n];
        float va, vb;
        if (region == 1) {
            va = wa - __bfloat162float(__float2bfloat16(wa));
            vb = wb - __bfloat162float(__float2bfloat16(wb));
        } else {
            va = wa; vb = wb;
        }
        unsigned u = bfpack(va, vb);
        int k16 = Ks >> 4, k8 = Ks & 15;
        int lane = ((n & 7) << 2) | ((k8 >> 1) & 3);
        int reg = (k8 >> 3) & 1;
        g_bpack[((k16 * 512 + (n >> 3)) * 32 + lane) * 2 + reg] = u;
        return;
    }
    int idx3 = idx2 - 128 * 4096;
    if (idx3 < 128 * 256) {
        // GRU stacked W'' -> fragments + bias
        int kp = idx3 >> 8, c = idx3 & 255;
        int Ks = kp << 1;
        int region = Ks >> 7;
        int k = Ks & 127;
        float wa = gru_wfull(gru_wih, gru_whh, k, c);
        float wb = gru_wfull(gru_wih, gru_whh, k + 1, c);
        float va, vb;
        if (region == 1) {
            va = wa - __bfloat162float(__float2bfloat16(wa));
            vb = wb - __bfloat162float(__float2bfloat16(wb));
        } else {
            va = wa; vb = wb;
        }
        unsigned u = bfpack(va, vb);
        int k16 = Ks >> 4, k8 = Ks & 15;
        int lane = ((c & 7) << 2) | ((k8 >> 1) & 3);
        int reg = (k8 >> 3) & 1;
        g_gpack[((k16 * 32 + (c >> 3)) * 32 + lane) * 2 + reg] = u;
        if (kp == 0) {
            float bias;
            if (c < 128) bias = gru_bih[c] + gru_bhh[c];
            else if (c < 192) bias = gru_bih[c];
            else bias = gru_bhh[c - 64];
            g_gbias[c] = bias;
        }
        return;
    }
    int idx4 = idx3 - 128 * 256;
    if (idx4 < 256 * 128) {
        // s2s_wihT transpose: [256,128] -> [128][256]
        int g = idx4 >> 7, k = idx4 & 127;
        g_s2s_wihT[k * 256 + g] = s2s_wih[idx4];
        return;
    }
    int idx5 = idx4 - 256 * 128;
    if (idx5 < 256 * 64) {
        // s2s_whhT transpose: [256,64] -> [64][256]
        int g = idx5 >> 6, k = idx5 & 63;
        g_s2s_whhT[k * 256 + g] = s2s_whh[idx5];
    }
}

// ---------------- lin0 + degree count + segment scan (fused) -----------------
__global__ void k_lin0(const float* __restrict__ nf, const float* __restrict__ w,
                       const float* __restrict__ b, const int* __restrict__ ei,
                       const int* __restrict__ gidx, int N, int E) {
    int idx = blockIdx.x * blockDim.x + threadIdx.x;
    if (idx < E) atomicAdd(&g_deg[ei[E + idx]], 1);
    if (idx < N) {
        int g = gidx[idx];
        atomicMin(&g_start[g], idx);
        atomicAdd(&g_cnt[g], 1);
    }
    if (idx >= N * DIM) return;
    int n = idx >> 6, d = idx & 63;
    float acc = b[d];
    #pragma unroll
    for (int k = 0; k < 30; k++) acc = fmaf(nf[n * 30 + k], w[k * DIM + d], acc);
    g_h[idx] = fmaxf(acc, 0.f);
    g_agg[idx] = 0.f;
}

// ---------------- templated fragment GEMM (R12-verified, bf16x3, 3 passes) ---
template <int N8TOT, typename OutT>
__global__ void __launch_bounds__(256, 2) k_gemm_frag(
        const unsigned* __restrict__ Ap, const unsigned* __restrict__ Bp,
        const float* __restrict__ bias, OutT* __restrict__ C, int M) {
    constexpr int LDC = N8TOT * 8;
    extern __shared__ __align__(16) unsigned sm[];
    const int tid = threadIdx.x;
    const int lane = tid & 31, warp = tid >> 5;
    const int wm = warp >> 2, wn = warp & 3;
    const int bm = blockIdx.y << 7, bn = blockIdx.x << 7;
    const uint4* Ap4 = reinterpret_cast<const uint4*>(Ap);
    const uint4* Bp4 = reinterpret_cast<const uint4*>(Bp);

    float acc[4][4][4];
    #pragma unroll
    for (int i = 0; i < 4; i++)
        #pragma unroll
        for (int j = 0; j < 4; j++)
            #pragma unroll
            for (int c = 0; c < 4; c++) acc[i][j][c] = 0.f;

    uint4 ra[2], rb[2];

    auto LDG = [&](int s) {
        #pragma unroll
        for (int l = 0; l < 2; l++) {
            int id = tid + (l << 8);
            {
                int la = id & 31, mt = (id >> 5) & 7, part = id >> 8;
                ra[l] = Ap4[(((size_t)((bm >> 4) + mt)) * 16 + (s + part * 8)) * 32 + la];
            }
            {
                int quad = id & 15, nt = (id >> 4) & 15, part = id >> 8;
                rb[l] = Bp4[((size_t)(s + part * 8) * N8TOT + (bn >> 3) + nt) * 16 + quad];
            }
        }
    };
    auto STS = [&](int buf) {
        #pragma unroll
        for (int l = 0; l < 2; l++) {
            int id = tid + (l << 8);
            {
                int la = id & 31, mt = (id >> 5) & 7, part = id >> 8;
                *reinterpret_cast<uint4*>(sm + buf * 2048 + part * 1024 + mt * 128 + la * 4) = ra[l];
            }
            {
                int quad = id & 15, nt = (id >> 4) & 15, part = id >> 8;
                *reinterpret_cast<uint4*>(sm + 8192 + buf * 2048 + part * 1024 + nt * 64 + quad * 4) = rb[l];
            }
        }
    };
    auto COMPUTE = [&](int buf) {
        unsigned a[4][4], b0[4][2], b1[4][2];
        const unsigned* Bb = sm + 8192 + buf * 2048;
        #pragma unroll
        for (int j = 0; j < 4; j++) {
            *reinterpret_cast<uint2*>(b0[j]) =
                *reinterpret_cast<const uint2*>(Bb + ((wn << 2) + j) * 64 + lane * 2);
            *reinterpret_cast<uint2*>(b1[j]) =
                *reinterpret_cast<const uint2*>(Bb + 1024 + ((wn << 2) + j) * 64 + lane * 2);
        }
        const unsigned* Ab = sm + buf * 2048;
        #pragma unroll
        for (int i = 0; i < 4; i++)
            *reinterpret_cast<uint4*>(a[i]) =
                *reinterpret_cast<const uint4*>(Ab + ((wm << 2) + i) * 128 + lane * 4);
        #pragma unroll
        for (int i = 0; i < 4; i++)
            #pragma unroll
            for (int j = 0; j < 4; j++)
                asm volatile(
                    "mma.sync.aligned.m16n8k16.row.col.f32.bf16.bf16.f32 "
                    "{%0,%1,%2,%3}, {%4,%5,%6,%7}, {%8,%9}, {%0,%1,%2,%3};"
                    : "+f"(acc[i][j][0]), "+f"(acc[i][j][1]),
                      "+f"(acc[i][j][2]), "+f"(acc[i][j][3])
                    : "r"(a[i][0]), "r"(a[i][1]), "r"(a[i][2]), "r"(a[i][3]),
                      "r"(b0[j][0]), "r"(b0[j][1]));
        #pragma unroll
        for (int i = 0; i < 4; i++)
            #pragma unroll
            for (int j = 0; j < 4; j++)
                asm volatile(
                    "mma.sync.aligned.m16n8k16.row.col.f32.bf16.bf16.f32 "
                    "{%0,%1,%2,%3}, {%4,%5,%6,%7}, {%8,%9}, {%0,%1,%2,%3};"
                    : "+f"(acc[i][j][0]), "+f"(acc[i][j][1]),
                      "+f"(acc[i][j][2]), "+f"(acc[i][j][3])
                    : "r"(a[i][0]), "r"(a[i][1]), "r"(a[i][2]), "r"(a[i][3]),
                      "r"(b1[j][0]), "r"(b1[j][1]));
        #pragma unroll
        for (int i = 0; i < 4; i++)
            *reinterpret_cast<uint4*>(a[i]) =
                *reinterpret_cast<const uint4*>(Ab + 1024 + ((wm << 2) + i) * 128 + lane * 4);
        #pragma unroll
        for (int i = 0; i < 4; i++)
            #pragma unroll
            for (int j = 0; j < 4; j++)
                asm volatile(
                    "mma.sync.aligned.m16n8k16.row.col.f32.bf16.bf16.f32 "
                    "{%0,%1,%2,%3}, {%4,%5,%6,%7}, {%8,%9}, {%0,%1,%2,%3};"
                    : "+f"(acc[i][j][0]), "+f"(acc[i][j][1]),
                      "+f"(acc[i][j][2]), "+f"(acc[i][j][3])
                    : "r"(a[i][0]), "r"(a[i][1]), "r"(a[i][2]), "r"(a[i][3]),
                      "r"(b0[j][0]), "r"(b0[j][1]));
    };

    LDG(0); STS(0);
    LDG(1); STS(1);
    __syncthreads();
    #pragma unroll 1
    for (int s = 0; s < 8; s += 2) {
        if (s < 6) LDG(s + 2);
        COMPUTE(s & 3);
        if (s < 6) STS((s + 2) & 3);
        if (s < 6) LDG(s + 3);
        COMPUTE((s + 1) & 3);
        if (s < 6) {
            STS((s + 3) & 3);
            __syncthreads();
        }
    }

    int g = lane >> 2, tg = lane & 3;
    #pragma unroll
    for (int i = 0; i < 4; i++) {
        int r0 = bm + (wm << 6) + (i << 4) + g;
        #pragma unroll
        for (int j = 0; j < 4; j++) {
            int col = bn + (wn << 5) + (j << 3) + (tg << 1);
            float b0 = bias[col], b1 = bias[col + 1];
            float v0 = acc[i][j][0] + b0, v1 = acc[i][j][1] + b1;
            float v2 = acc[i][j][2] + b0, v3 = acc[i][j][3] + b1;
            if (r0 < M) {
                if constexpr (std::is_same<OutT, __half>::value)
                    *reinterpret_cast<__half2*>(C + (size_t)r0 * LDC + col) = __floats2half2_rn(v0, v1);
                else
                    *reinterpret_cast<float2*>(C + (size_t)r0 * LDC + col) = make_float2(v0, v1);
            }
            if (r0 + 8 < M) {
                if constexpr (std::is_same<OutT, __half>::value)
                    *reinterpret_cast<__half2*>(C + (size_t)(r0 + 8) * LDC + col) = __floats2half2_rn(v2, v3);
                else
                    *reinterpret_cast<float2*>(C + (size_t)(r0 + 8) * LDC + col) = make_float2(v2, v3);
            }
        }
    }
}

// ---------------- per-edge message: 512 thr = 16 edges/block, half2 loads ----
__global__ void k_msg(const int* __restrict__ ei, int E) {
    __shared__ float f_sh[16][DIM];
    int t = threadIdx.x;
    int eg = t >> 5, tl = t & 31;
    int e = blockIdx.x * 16 + eg;
    if (e < E) {
        int src = ei[e];
        f_sh[eg][tl] = g_h[(size_t)src * DIM + tl];
        f_sh[eg][tl + 32] = g_h[(size_t)src * DIM + tl + 32];
    }
    __syncthreads();
    if (e >= E) return;
    const __half2* ew = reinterpret_cast<const __half2*>(g_ew16 + (size_t)e * 4096) + tl;
    const float* f = f_sh[eg];
    float acc0 = 0.f, acc1 = 0.f;
    #pragma unroll
    for (int i = 0; i < DIM; i++) {
        float2 w = __half22float2(ew[i * 32]);
        acc0 = fmaf(f[i], w.x, acc0);
        acc1 = fmaf(f[i], w.y, acc1);
    }
    int dst = ei[E + e];
    atomicAdd(&g_agg[(size_t)dst * DIM + 2 * tl], acc0);
    atomicAdd(&g_agg[(size_t)dst * DIM + 2 * tl + 1], acc1);
}

// ---------------- X* pack for GRU GEMM: X=[m|h]; inv-deg inline --------------
__global__ void k_xpack(const float* __restrict__ conv_b, int N) {
    int idx = blockIdx.x * blockDim.x + threadIdx.x;
    if (idx >= N * 64) return;
    int n = idx >> 6, jp = idx & 63;
    int j0 = jp << 1;
    float a, b;
    if (j0 < 64) {
        float inv = 1.f / fmaxf((float)g_deg[n], 1.f);
        a = fmaxf(fmaf(g_agg[n * 64 + j0], inv, conv_b[j0]), 0.f);
        b = fmaxf(fmaf(g_agg[n * 64 + j0 + 1], inv, conv_b[j0 + 1]), 0.f);
        g_agg[n * 64 + j0] = 0.f;
        g_agg[n * 64 + j0 + 1] = 0.f;
    } else {
        a = g_h[n * 64 + (j0 - 64)];
        b = g_h[n * 64 + (j0 - 63)];
    }
    float a0 = __bfloat162float(__float2bfloat16(a));
    float b0 = __bfloat162float(__float2bfloat16(b));
    unsigned p0 = bfpack(a, b);
    unsigned p1 = bfpack(a - a0, b - b0);
    int m16 = n >> 4, r16 = n & 15;
    int k8 = j0 & 15;
    int lane = ((r16 & 7) << 2) | ((k8 >> 1) & 3);
    int reg = (r16 >> 3) | (((k8 >> 3) & 1) << 1);
    size_t base = ((size_t)m16 * 16 + (j0 >> 4)) * 128 + lane * 4 + reg;
    g_xpack[base] = p0;
    g_xpack[base + (size_t)8 * 128] = p1;
}

// ---------------- GRU combine from stacked gates -----------------------------
__global__ void k_gru_combine(int N) {
    int idx = blockIdx.x * blockDim.x + threadIdx.x;
    if (idx >= N * DIM) return;
    int n = idx >> 6, d = idx & 63;
    const float* g = &g_gates[(size_t)n * 256];
    float r = sigf(g[d]);
    float z = sigf(g[64 + d]);
    float nn = tanhf(fmaf(r, g[192 + d], g[128 + d]));
    float hold = g_h[idx];
    g_h[idx] = fmaf(z, hold - nn, nn);
}

// ---------------- fused Set2Set (3 steps) + FC head: one block per graph -----
__global__ void k_s2s_all(const float* __restrict__ bih, const float* __restrict__ bhh,
                          const float* __restrict__ fc1_w, const float* __restrict__ fc1_b,
                          const float* __restrict__ fc2_w, const float* __restrict__ fc2_b,
                          float* __restrict__ out) {
    int b = blockIdx.x, t = threadIdx.x;
    __shared__ float q_sh[128], h_sh[64], lc_sh[64], gates[256], red[256], rpart[4][64];
    if (t < 128) q_sh[t] = 0.f;
    if (t < 64) { h_sh[t] = 0.f; lc_sh[t] = 0.f; }
    int s = g_start[b], c = g_cnt[b];
    if (s == 0x7fffffff) s = 0;
    __syncthreads();
    for (int step = 0; step < 3; step++) {
        float acc = bih[t] + bhh[t];
        #pragma unroll 8
        for (int k = 0; k < 128; k++) acc = fmaf(q_sh[k], g_s2s_wihT[k * 256 + t], acc);
        #pragma unroll 8
        for (int k = 0; k < 64; k++) acc = fmaf(h_sh[k], g_s2s_whhT[k * 256 + t], acc);
        gates[t] = acc;
        __syncthreads();
        if (t < 64) {
            float ig = sigf(gates[t]), fg = sigf(gates[64 + t]);
            float gg = tanhf(gates[128 + t]), og = sigf(gates[192 + t]);
            float cc = fmaf(fg, lc_sh[t], ig * gg);
            lc_sh[t] = cc;
            h_sh[t] = og * tanhf(cc);
        }
        __syncthreads();
        float lmax = -CUDART_INF_F;
        for (int n = s + t; n < s + c; n += 256) {
            const float* hp = &g_h[(size_t)n * DIM];
            float d = 0.f;
            #pragma unroll 8
            for (int k = 0; k < DIM; k++) d = fmaf(hp[k], h_sh[k], d);
            g_e[n] = d;
            lmax = fmaxf(lmax, d);
        }
        red[t] = lmax;
        __syncthreads();
        for (int off = 128; off > 0; off >>= 1) {
            if (t < off) red[t] = fmaxf(red[t], red[t + off]);
            __syncthreads();
        }
        float emax = red[0];
        __syncthreads();
        float lsum = 0.f;
        for (int n = s + t; n < s + c; n += 256) lsum += expf(g_e[n] - emax);
        red[t] = lsum;
        __syncthreads();
        for (int off = 128; off > 0; off >>= 1) {
            if (t < off) red[t] += red[t + off];
            __syncthreads();
        }
        float inv = red[0] > 0.f ? 1.f / red[0] : 0.f;
        __syncthreads();
        int d = t & 63, sub = t >> 6;
        float acc2 = 0.f;
        for (int n = s + sub; n < s + c; n += 4)
            acc2 = fmaf(expf(g_e[n] - emax), g_h[(size_t)n * DIM + d], acc2);
        rpart[sub][d] = acc2;
        __syncthreads();
        if (t < 64) {
            q_sh[64 + t] = (rpart[0][t] + rpart[1][t] + rpart[2][t] + rpart[3][t]) * inv;
            q_sh[t] = h_sh[t];
        }
        __syncthreads();
    }
    if (t < 64) {
        float acc = fc1_b[t];
        #pragma unroll 8
        for (int k = 0; k < 128; k++) acc = fmaf(q_sh[k], fc1_w[k * DIM + t], acc);
        red[t] = fmaxf(acc, 0.f) * fc2_w[t];
    }
    __syncthreads();
    for (int off = 32; off > 0; off >>= 1) {
        if (t < off) red[t] += red[t + off];
        __syncthreads();
    }
    if (t == 0) out[b] = red[0] + fc2_b[0];
}

// ---------------- launch -----------------------------------------------------
extern "C" void kernel_launch(void* const* d_in, const int* in_sizes, int n_in,
                              void* d_out, int out_size) {
    const int N = in_sizes[0] / 30;
    const int E = in_sizes[1] / 11;
    const int B = out_size;

    const float* nf   = (const float*)d_in[0];
    const float* ef   = (const float*)d_in[1];
    const int*   ei   = (const int*)d_in[2];
    const int*   gidx = (const int*)d_in[3];
    int wb = (in_sizes[4] == 1) ? 5 : 4;
    const float* lin0_w  = (const float*)d_in[wb + 0];
    const float* lin0_b  = (const float*)d_in[wb + 1];
    const float* enn_w1  = (const float*)d_in[wb + 2];
    const float* enn_b1  = (const float*)d_in[wb + 3];
    const float* enn_w2  = (const float*)d_in[wb + 4];
    const float* enn_b2  = (const float*)d_in[wb + 5];
    const float* conv_b  = (const float*)d_in[wb + 6];
    const float* gru_wih = (const float*)d_in[wb + 7];
    const float* gru_whh = (const float*)d_in[wb + 8];
    const float* gru_bih = (const float*)d_in[wb + 9];
    const float* gru_bhh = (const float*)d_in[wb + 10];
    const float* s2s_wih = (const float*)d_in[wb + 11];
    const float* s2s_whh = (const float*)d_in[wb + 12];
    const float* s2s_bih = (const float*)d_in[wb + 13];
    const float* s2s_bhh = (const float*)d_in[wb + 14];
    const float* fc1_w   = (const float*)d_in[wb + 15];
    const float* fc1_b   = (const float*)d_in[wb + 16];
    const float* fc2_w   = (const float*)d_in[wb + 17];
    const float* fc2_b   = (const float*)d_in[wb + 18];
    float* out = (float*)d_out;

    float *p_gbias, *p_gates;
    unsigned *p_ap, *p_bp, *p_xp, *p_gp;
    __half *p_ew;
    cudaGetSymbolAddress((void**)&p_ap, g_apack);
    cudaGetSymbolAddress((void**)&p_bp, g_bpack);
    cudaGetSymbolAddress((void**)&p_xp, g_xpack);
    cudaGetSymbolAddress((void**)&p_gp, g_gpack);
    cudaGetSymbolAddress((void**)&p_gbias, g_gbias);
    cudaGetSymbolAddress((void**)&p_gates, g_gates);
    cudaGetSymbolAddress((void**)&p_ew, g_ew16);

    cudaFuncSetAttribute(k_gemm_frag<512, __half>,
                         cudaFuncAttributeMaxDynamicSharedMemorySize, 65536);
    cudaFuncSetAttribute(k_gemm_frag<32, float>,
                         cudaFuncAttributeMaxDynamicSharedMemorySize, 65536);

    // 1: mega-prep (A*, B*, W'', s2s transposes, deg/start/cnt init)
    {
        int total = E * 64 + 128 * 4096 + 128 * 256 + 256 * 128 + 256 * 64;
        k_prep_all<<<(total + 255) / 256, 256>>>(ef, enn_w1, enn_b1, enn_w2,
                                                 gru_wih, gru_whh, gru_bih, gru_bhh,
                                                 s2s_wih, s2s_whh, E, N);
    }
    // 2: lin0 + degree count + segment scan
    k_lin0<<<(N * DIM + 255) / 256, 256>>>(nf, lin0_w, lin0_b, ei, gidx, N, E);
    // 3: big GEMM
    {
        dim3 grid(4096 / 128, (E + 127) / 128);
        k_gemm_frag<512, __half><<<grid, 256, 65536>>>(p_ap, p_bp, enn_b2, p_ew, E);
    }
    // 4+: 3 message-passing + GRU iterations
    dim3 ggrid(256 / 128, (N + 127) / 128);
    for (int it = 0; it < 3; it++) {
        k_msg<<<(E + 15) / 16, 512>>>(ei, E);
        k_xpack<<<(N * 64 + 255) / 256, 256>>>(conv_b, N);
        k_gemm_frag<32, float><<<ggrid, 256, 65536>>>(p_xp, p_gp, p_gbias, p_gates, N);
        k_gru_combine<<<(N * DIM + 255) / 256, 256>>>(N);
    }

    // Set2Set + FC head
    k_s2s_all<<<B, 256>>>(s2s_bih, s2s_bhh, fc1_w, fc1_b, fc2_w, fc2_b, out);
}